// round 11
// baseline (speedup 1.0000x reference)
#include <cuda_runtime.h>
#include <cuda_fp16.h>

#define CH      128
#define NMAX    10000
#define EMAX    640000
#define SLOTS   256

typedef unsigned long long ull;

// ---------------- device scratch ----------------
__device__ __align__(16) __half2 g_Ah[NMAX * CH / 2]; // fp16(x @ W1[:128])
__device__ __align__(16) float g_Bp[NMAX * CH];       // x @ W1[128:] + b1
__device__ __align__(16) float g_H [NMAX * CH];
__device__ int g_cnt[NMAX];
__device__ __align__(16) ull g_pay[(size_t)NMAX * SLOTS];

// ---------------- bucket scatter (R5-proven 4/thread) ----------------
__global__ __launch_bounds__(256)
void zero_cnt_kernel(int* __restrict__ cnt, int n) {
    int i = blockIdx.x * blockDim.x + threadIdx.x;
    if (i < n) cnt[i] = 0;
}

__global__ __launch_bounds__(256)
void scatter_kernel(const int* __restrict__ ei, const float* __restrict__ ea,
                    int* __restrict__ cnt, ull* __restrict__ pay, int E) {
    int i0 = (blockIdx.x * blockDim.x + threadIdx.x) * 4;
    if (i0 + 3 < E) {
        int4   rows = *(const int4*)(ei + i0);
        int4   cols = *(const int4*)(ei + E + i0);
        float4 a    = *(const float4*)(ea + i0);
        int   r[4] = {rows.x, rows.y, rows.z, rows.w};
        int   c[4] = {cols.x, cols.y, cols.z, cols.w};
        float v[4] = {a.x, a.y, a.z, a.w};
#pragma unroll
        for (int k = 0; k < 4; k++) {
            int slot = atomicAdd(cnt + c[k], 1);
            if (slot < SLOTS)
                pay[((size_t)c[k] << 8) + slot] =
                    ((ull)__float_as_uint(v[k]) << 32) | (unsigned)r[k];
        }
    } else {
        for (int i = i0; i < E; i++) {
            int c = ei[E + i];
            int slot = atomicAdd(cnt + c, 1);
            if (slot < SLOTS)
                pay[((size_t)c << 8) + slot] =
                    ((ull)__float_as_uint(ea[i]) << 32) | (unsigned)ei[i];
        }
    }
}

// ---------------- SGEMM tiles: BM=128, BN=64, BK=16, TM=8, TN=4 ----------------
#define BM 128
#define BN 64
#define BK 16
#define TM 8
#define TN 4

// fused dual GEMM: y<2 -> Ah (fp16 out); y>=2 -> Bp (fp32 out, +b1)
__global__ __launch_bounds__(256)
void gemm_w1_kernel(const float* __restrict__ X, const float* __restrict__ W1,
                    const float* __restrict__ b1,
                    __half2* __restrict__ Ah, float* __restrict__ Bpout, int M) {
    __shared__ __align__(16) float AsT[BK][BM];
    __shared__ __align__(16) float Bs [BK][BN];

    const float* B = (blockIdx.y < 2) ? W1 : (W1 + CH * CH);
    int colBase = (blockIdx.y & 1) * BN;

    int tid = threadIdx.x;
    int tx = tid & 15;
    int ty = tid >> 4;
    int rowBase = blockIdx.x * BM;

    float acc[TM][TN];
#pragma unroll
    for (int i = 0; i < TM; i++)
#pragma unroll
        for (int j = 0; j < TN; j++) acc[i][j] = 0.f;

    for (int k0 = 0; k0 < CH; k0 += BK) {
#pragma unroll
        for (int l = 0; l < 2; l++) {
            int f = tid + l * 256;
            int r = f >> 2;
            int kc = (f & 3) * 4;
            float4 v = make_float4(0.f, 0.f, 0.f, 0.f);
            int gr = rowBase + r;
            if (gr < M) v = *(const float4*)(X + (size_t)gr * CH + k0 + kc);
            AsT[kc + 0][r] = v.x;
            AsT[kc + 1][r] = v.y;
            AsT[kc + 2][r] = v.z;
            AsT[kc + 3][r] = v.w;
        }
        {
            int r = tid >> 4;
            int c = (tid & 15) * 4;
            float4 v = *(const float4*)(B + (size_t)(k0 + r) * CH + colBase + c);
            *(float4*)&Bs[r][c] = v;
        }
        __syncthreads();

#pragma unroll
        for (int kk = 0; kk < BK; kk++) {
            float a[TM], b[TN];
            float4 a0 = *(const float4*)&AsT[kk][ty * TM];
            float4 a1 = *(const float4*)&AsT[kk][ty * TM + 4];
            a[0]=a0.x; a[1]=a0.y; a[2]=a0.z; a[3]=a0.w;
            a[4]=a1.x; a[5]=a1.y; a[6]=a1.z; a[7]=a1.w;
            float4 b0 = *(const float4*)&Bs[kk][tx * TN];
            b[0]=b0.x; b[1]=b0.y; b[2]=b0.z; b[3]=b0.w;
#pragma unroll
            for (int i = 0; i < TM; i++)
#pragma unroll
                for (int j = 0; j < TN; j++)
                    acc[i][j] = fmaf(a[i], b[j], acc[i][j]);
        }
        __syncthreads();
    }

    int c = colBase + tx * TN;
    if (blockIdx.y < 2) {
        // fp16 output to Ah
#pragma unroll
        for (int i = 0; i < TM; i++) {
            int gr = rowBase + ty * TM + i;
            if (gr >= M) continue;
            __half2 h0 = __floats2half2_rn(acc[i][0], acc[i][1]);
            __half2 h1 = __floats2half2_rn(acc[i][2], acc[i][3]);
            uint2 o;
            o.x = *(unsigned*)&h0;
            o.y = *(unsigned*)&h1;
            *(uint2*)(Ah + (size_t)gr * (CH / 2) + c / 2) = o;
        }
    } else {
        float4 bias = *(const float4*)(b1 + c);
#pragma unroll
        for (int i = 0; i < TM; i++) {
            int gr = rowBase + ty * TM + i;
            if (gr >= M) continue;
            float4 o;
            o.x = acc[i][0] + bias.x;
            o.y = acc[i][1] + bias.y;
            o.z = acc[i][2] + bias.z;
            o.w = acc[i][3] + bias.w;
            *(float4*)(Bpout + (size_t)gr * CH + c) = o;
        }
    }
}

// out = H @ W2 + deg[m]*b2[n]
__global__ __launch_bounds__(256)
void gemm_out_kernel(const float* __restrict__ H, const float* __restrict__ W2,
                     float* __restrict__ C, int M,
                     const int* __restrict__ deg, const float* __restrict__ b2) {
    __shared__ __align__(16) float AsT[BK][BM];
    __shared__ __align__(16) float Bs [BK][BN];

    int tid = threadIdx.x;
    int tx = tid & 15;
    int ty = tid >> 4;
    int rowBase = blockIdx.x * BM;
    int colBase = blockIdx.y * BN;

    float acc[TM][TN];
#pragma unroll
    for (int i = 0; i < TM; i++)
#pragma unroll
        for (int j = 0; j < TN; j++) acc[i][j] = 0.f;

    for (int k0 = 0; k0 < CH; k0 += BK) {
#pragma unroll
        for (int l = 0; l < 2; l++) {
            int f = tid + l * 256;
            int r = f >> 2;
            int kc = (f & 3) * 4;
            float4 v = make_float4(0.f, 0.f, 0.f, 0.f);
            int gr = rowBase + r;
            if (gr < M) v = *(const float4*)(H + (size_t)gr * CH + k0 + kc);
            AsT[kc + 0][r] = v.x;
            AsT[kc + 1][r] = v.y;
            AsT[kc + 2][r] = v.z;
            AsT[kc + 3][r] = v.w;
        }
        {
            int r = tid >> 4;
            int c = (tid & 15) * 4;
            float4 v = *(const float4*)(W2 + (size_t)(k0 + r) * CH + colBase + c);
            *(float4*)&Bs[r][c] = v;
        }
        __syncthreads();

#pragma unroll
        for (int kk = 0; kk < BK; kk++) {
            float a[TM], b[TN];
            float4 a0 = *(const float4*)&AsT[kk][ty * TM];
            float4 a1 = *(const float4*)&AsT[kk][ty * TM + 4];
            a[0]=a0.x; a[1]=a0.y; a[2]=a0.z; a[3]=a0.w;
            a[4]=a1.x; a[5]=a1.y; a[6]=a1.z; a[7]=a1.w;
            float4 b0 = *(const float4*)&Bs[kk][tx * TN];
            b[0]=b0.x; b[1]=b0.y; b[2]=b0.z; b[3]=b0.w;
#pragma unroll
            for (int i = 0; i < TM; i++)
#pragma unroll
                for (int j = 0; j < TN; j++)
                    acc[i][j] = fmaf(a[i], b[j], acc[i][j]);
        }
        __syncthreads();
    }

#pragma unroll
    for (int i = 0; i < TM; i++) {
        int gr = rowBase + ty * TM + i;
        if (gr >= M) continue;
        float rs = (float)deg[gr];
        int c = colBase + tx * TN;
        float4 o;
        o.x = fmaf(rs, b2[c + 0], acc[i][0]);
        o.y = fmaf(rs, b2[c + 1], acc[i][1]);
        o.z = fmaf(rs, b2[c + 2], acc[i][2]);
        o.w = fmaf(rs, b2[c + 3], acc[i][3]);
        *(float4*)(C + (size_t)gr * CH + c) = o;
    }
}

// ---------------- edge aggregation: warp/node, fp16 A gathers, f32x2 math --------
__global__ void __launch_bounds__(256, 6)
edge_kernel(const __half2* __restrict__ Ah, const float* __restrict__ Bpb,
            const int* __restrict__ cnt, const ull* __restrict__ pay,
            float* __restrict__ H, int N) {
    int w = (blockIdx.x * blockDim.x + threadIdx.x) >> 5;
    int lane = threadIdx.x & 31;
    if (w >= N) return;
    int c4 = lane * 4;

    ulonglong2 bvp = *(const ulonglong2*)(Bpb + (size_t)w * CH + c4);
    ull bv0 = bvp.x, bv1 = bvp.y;
    ull acc0 = 0ull, acc1 = 0ull;

    int n = cnt[w];
    if (n > SLOTS) n = SLOTS;
    size_t base = (size_t)w << 8;
    int h2off = lane * 2;                  // half2 index within row (row = 64 half2)

    for (int j = 0; j < n; j += 32) {
        ull p = 0;
        if (j + lane < n) p = pay[base + j + lane];
        int m = n - j; if (m > 32) m = 32;
        for (int k = 0; k < m; k++) {
            ull pk = __shfl_sync(0xFFFFFFFFu, p, k);
            unsigned rbits = (unsigned)pk;
            unsigned abits = (unsigned)(pk >> 32);
            ull aa;
            asm("mov.b64 %0, {%1, %1};" : "=l"(aa) : "r"(abits));
            uint2 hv = *(const uint2*)(Ah + (((size_t)rbits) << 6) + h2off);
            float2 f0 = __half22float2(*(__half2*)&hv.x);
            float2 f1 = __half22float2(*(__half2*)&hv.y);
            ull av0, av1;
            asm("mov.b64 %0, {%1, %2};" : "=l"(av0) : "f"(f0.x), "f"(f0.y));
            asm("mov.b64 %0, {%1, %2};" : "=l"(av1) : "f"(f1.x), "f"(f1.y));
            ull t0, t1;
            asm("fma.rn.f32x2 %0, %1, %2, %3;" : "=l"(t0) : "l"(aa), "l"(av0), "l"(bv0));
            asm("fma.rn.f32x2 %0, %1, %2, %3;" : "=l"(t1) : "l"(aa), "l"(av1), "l"(bv1));
            unsigned lo0, hi0, lo1, hi1;
            asm("mov.b64 {%0, %1}, %2;" : "=r"(lo0), "=r"(hi0) : "l"(t0));
            asm("mov.b64 {%0, %1}, %2;" : "=r"(lo1), "=r"(hi1) : "l"(t1));
            lo0 = __float_as_uint(fmaxf(__uint_as_float(lo0), 0.f));
            hi0 = __float_as_uint(fmaxf(__uint_as_float(hi0), 0.f));
            lo1 = __float_as_uint(fmaxf(__uint_as_float(lo1), 0.f));
            hi1 = __float_as_uint(fmaxf(__uint_as_float(hi1), 0.f));
            asm("mov.b64 %0, {%1, %2};" : "=l"(t0) : "r"(lo0), "r"(hi0));
            asm("mov.b64 %0, {%1, %2};" : "=l"(t1) : "r"(lo1), "r"(hi1));
            asm("add.rn.f32x2 %0, %1, %2;" : "=l"(acc0) : "l"(acc0), "l"(t0));
            asm("add.rn.f32x2 %0, %1, %2;" : "=l"(acc1) : "l"(acc1), "l"(t1));
        }
    }
    ulonglong2 o;
    o.x = acc0; o.y = acc1;
    *(ulonglong2*)(H + (size_t)w * CH + c4) = o;
}

// ---------------- launch ----------------
extern "C" void kernel_launch(void* const* d_in, const int* in_sizes, int n_in,
                              void* d_out, int out_size) {
    const float* x  = (const float*)d_in[0];
    const int*   ei = (const int*)d_in[1];     // int32 [2, E]
    const float* ea = (const float*)d_in[2];
    const float* W1 = (const float*)d_in[3];
    const float* b1 = (const float*)d_in[4];
    const float* W2 = (const float*)d_in[5];
    const float* b2 = (const float*)d_in[6];
    float* out = (float*)d_out;

    int N = in_sizes[0] / CH;
    int E = in_sizes[2];

    __half2 *pAh;
    float *pBp, *pH;
    int *pcnt;
    ull *ppay;
    cudaGetSymbolAddress((void**)&pAh,  g_Ah);
    cudaGetSymbolAddress((void**)&pBp,  g_Bp);
    cudaGetSymbolAddress((void**)&pH,   g_H);
    cudaGetSymbolAddress((void**)&pcnt, g_cnt);
    cudaGetSymbolAddress((void**)&ppay, g_pay);

    // bucket scatter (by receiving node = col)
    zero_cnt_kernel<<<(N + 255) / 256, 256>>>(pcnt, N);
    int sthreads = (E + 3) / 4;
    scatter_kernel<<<(sthreads + 255) / 256, 256>>>(ei, ea, pcnt, ppay, E);

    // fused node-level GEMMs: g_Ah = fp16(x@W1[:128]), g_Bp = x@W1[128:] + b1
    dim3 g1((N + BM - 1) / BM, 4);
    gemm_w1_kernel<<<g1, 256>>>(x, W1, b1, pAh, pBp, N);

    // per-node ReLU-message aggregation (warp per node)
    edge_kernel<<<(N * 32 + 255) / 256, 256>>>(pAh, pBp, pcnt, ppay, pH, N);

    // out = H @ W2 + deg * b2
    dim3 g2((N + BM - 1) / BM, CH / BN);
    gemm_out_kernel<<<g2, 256>>>(pH, W2, out, N, pcnt, b2);
}

// round 12
// speedup vs baseline: 1.6482x; 1.6482x over previous
#include <cuda_runtime.h>
#include <cuda_fp16.h>
#include <mma.h>

using namespace nvcuda::wmma;

#define CH      128
#define NMAX    10000
#define EMAX    640000
#define SLOTS   256
#define PADROWS 64              // store_matrix_sync may write full 16-row tiles past M

#define XH_STRIDE 136           // 128 + 8 halves  (row = 272B, mult of 16)
#define WH_STRIDE 72            // 64 + 8 halves   (row = 144B, mult of 16)
#define CS_STRIDE 68            // 64 + 4 floats   (row = 272B, mult of 16)

typedef unsigned long long ull;

// ---------------- device scratch ----------------
__device__ __align__(16) float   g_A [(NMAX + PADROWS) * CH];  // x @ W1[:128]
__device__ __align__(16) float   g_Bp[(NMAX + PADROWS) * CH];  // x @ W1[128:] + b1
__device__ __align__(16) __half2 g_Hh[NMAX * CH / 2];          // fp16 aggregated hidden
__device__ int g_cnt[NMAX];
__device__ __align__(16) ull g_pay[(size_t)NMAX * SLOTS];

// ---------------- bucket scatter (R5-proven 4/thread) ----------------
__global__ __launch_bounds__(256)
void zero_cnt_kernel(int* __restrict__ cnt, int n) {
    int i = blockIdx.x * blockDim.x + threadIdx.x;
    if (i < n) cnt[i] = 0;
}

__global__ __launch_bounds__(256)
void scatter_kernel(const int* __restrict__ ei, const float* __restrict__ ea,
                    int* __restrict__ cnt, ull* __restrict__ pay, int E) {
    int i0 = (blockIdx.x * blockDim.x + threadIdx.x) * 4;
    if (i0 + 3 < E) {
        int4   rows = *(const int4*)(ei + i0);
        int4   cols = *(const int4*)(ei + E + i0);
        float4 a    = *(const float4*)(ea + i0);
        int   r[4] = {rows.x, rows.y, rows.z, rows.w};
        int   c[4] = {cols.x, cols.y, cols.z, cols.w};
        float v[4] = {a.x, a.y, a.z, a.w};
#pragma unroll
        for (int k = 0; k < 4; k++) {
            int slot = atomicAdd(cnt + c[k], 1);
            if (slot < SLOTS)
                pay[((size_t)c[k] << 8) + slot] =
                    ((ull)__float_as_uint(v[k]) << 32) | (unsigned)r[k];
        }
    } else {
        for (int i = i0; i < E; i++) {
            int c = ei[E + i];
            int slot = atomicAdd(cnt + c, 1);
            if (slot < SLOTS)
                pay[((size_t)c << 8) + slot] =
                    ((ull)__float_as_uint(ea[i]) << 32) | (unsigned)ei[i];
        }
    }
}

// ---------------- GEMM 1 (WMMA): A = x@W1a ; Bp = x@W1b + b1 -------------------
// grid (ceil(M/64), 4): ct = blockIdx.y; which = ct>>1 (0->A, 1->Bp); ncol = (ct&1)*64
__global__ __launch_bounds__(256)
void gemm_w1_wmma(const float* __restrict__ X, const float* __restrict__ W1,
                  const float* __restrict__ b1,
                  float* __restrict__ Aout, float* __restrict__ Bpout, int M) {
    __shared__ __align__(16) __half Xh[64 * XH_STRIDE];
    __shared__ __align__(16) __half Wh[128 * WH_STRIDE];
    __shared__ __align__(16) float  bias_t[16 * 64];

    int tid = threadIdx.x;
    int ct = blockIdx.y;
    int which = ct >> 1;
    int ncol = (ct & 1) * 64;
    const float* W = W1 + which * CH * CH;
    int rowBase = blockIdx.x * 64;

    // X tile 64x128 -> fp16 smem
#pragma unroll
    for (int i = 0; i < 8; i++) {
        int s = tid + i * 256;          // 0..2047 float4 slots
        int r = s >> 5;
        int c4 = (s & 31) * 4;
        float4 v = make_float4(0.f, 0.f, 0.f, 0.f);
        int gr = rowBase + r;
        if (gr < M) v = *(const float4*)(X + (size_t)gr * CH + c4);
        __half2 h0 = __floats2half2_rn(v.x, v.y);
        __half2 h1 = __floats2half2_rn(v.z, v.w);
        uint2 u; u.x = *(unsigned*)&h0; u.y = *(unsigned*)&h1;
        *(uint2*)&Xh[r * XH_STRIDE + c4] = u;
    }
    // W tile 128x64 -> fp16 smem
#pragma unroll
    for (int i = 0; i < 8; i++) {
        int s = tid + i * 256;
        int r = s >> 4;
        int c4 = (s & 15) * 4;
        float4 v = *(const float4*)(W + (size_t)r * CH + ncol + c4);
        __half2 h0 = __floats2half2_rn(v.x, v.y);
        __half2 h1 = __floats2half2_rn(v.z, v.w);
        uint2 u; u.x = *(unsigned*)&h0; u.y = *(unsigned*)&h1;
        *(uint2*)&Wh[r * WH_STRIDE + c4] = u;
    }
    if (which) {
#pragma unroll
        for (int i = 0; i < 4; i++) {
            int s = tid + i * 256;      // 0..1023
            bias_t[s] = b1[ncol + (s & 63)];
        }
    }
    __syncthreads();

    int wid = tid >> 5;
    int wr = wid >> 1;                  // 0..3 -> 16-row strip
    int wc = wid & 1;                   // 0..1 -> 32-col strip

    fragment<accumulator, 16, 16, 16, float> fc0, fc1;
    if (which) {
        load_matrix_sync(fc0, &bias_t[wc * 32], 64, mem_row_major);
        load_matrix_sync(fc1, &bias_t[wc * 32 + 16], 64, mem_row_major);
    } else {
        fill_fragment(fc0, 0.f);
        fill_fragment(fc1, 0.f);
    }

#pragma unroll
    for (int k0 = 0; k0 < 128; k0 += 16) {
        fragment<matrix_a, 16, 16, 16, __half, row_major> fa;
        fragment<matrix_b, 16, 16, 16, __half, row_major> fb0, fb1;
        load_matrix_sync(fa, &Xh[wr * 16 * XH_STRIDE + k0], XH_STRIDE);
        load_matrix_sync(fb0, &Wh[k0 * WH_STRIDE + wc * 32], WH_STRIDE);
        load_matrix_sync(fb1, &Wh[k0 * WH_STRIDE + wc * 32 + 16], WH_STRIDE);
        mma_sync(fc0, fa, fb0, fc0);
        mma_sync(fc1, fa, fb1, fc1);
    }

    float* Cout = which ? Bpout : Aout;
    int gr0 = rowBase + wr * 16;        // padded buffers: OOB rows land in pad
    store_matrix_sync(Cout + (size_t)gr0 * CH + ncol + wc * 32,      fc0, CH, mem_row_major);
    store_matrix_sync(Cout + (size_t)gr0 * CH + ncol + wc * 32 + 16, fc1, CH, mem_row_major);
}

// ---------------- GEMM 2 (WMMA): out = H @ W2 + deg[m]*b2[n] -------------------
__global__ __launch_bounds__(256)
void gemm_out_wmma(const __half2* __restrict__ Hh, const float* __restrict__ W2,
                   float* __restrict__ Cg, int M,
                   const int* __restrict__ deg, const float* __restrict__ b2) {
    __shared__ __align__(16) __half Hs[64 * XH_STRIDE];   // reused as float Cs[64][68]
    __shared__ __align__(16) __half Ws[128 * WH_STRIDE];

    int tid = threadIdx.x;
    int rowBase = blockIdx.x * 64;
    int colBase = blockIdx.y * 64;

    // H tile 64x128 halves
#pragma unroll
    for (int i = 0; i < 8; i++) {
        int s = tid + i * 256;          // 0..2047 (4-half slots)
        int r = s >> 5;
        int ch4 = (s & 31) * 4;
        uint2 u = make_uint2(0u, 0u);
        int gr = rowBase + r;
        if (gr < M) u = *(const uint2*)((const __half*)Hh + (size_t)gr * CH + ch4);
        *(uint2*)&Hs[r * XH_STRIDE + ch4] = u;
    }
    // W2 tile 128x64 -> fp16
#pragma unroll
    for (int i = 0; i < 8; i++) {
        int s = tid + i * 256;
        int r = s >> 4;
        int c4 = (s & 15) * 4;
        float4 v = *(const float4*)(W2 + (size_t)r * CH + colBase + c4);
        __half2 h0 = __floats2half2_rn(v.x, v.y);
        __half2 h1 = __floats2half2_rn(v.z, v.w);
        uint2 u; u.x = *(unsigned*)&h0; u.y = *(unsigned*)&h1;
        *(uint2*)&Ws[r * WH_STRIDE + c4] = u;
    }
    __syncthreads();

    int wid = tid >> 5;
    int wr = wid >> 1;
    int wc = wid & 1;

    fragment<accumulator, 16, 16, 16, float> fc0, fc1;
    fill_fragment(fc0, 0.f);
    fill_fragment(fc1, 0.f);

#pragma unroll
    for (int k0 = 0; k0 < 128; k0 += 16) {
        fragment<matrix_a, 16, 16, 16, __half, row_major> fa;
        fragment<matrix_b, 16, 16, 16, __half, row_major> fb0, fb1;
        load_matrix_sync(fa, &Hs[wr * 16 * XH_STRIDE + k0], XH_STRIDE);
        load_matrix_sync(fb0, &Ws[k0 * WH_STRIDE + wc * 32], WH_STRIDE);
        load_matrix_sync(fb1, &Ws[k0 * WH_STRIDE + wc * 32 + 16], WH_STRIDE);
        mma_sync(fc0, fa, fb0, fc0);
        mma_sync(fc1, fa, fb1, fc1);
    }

    __syncthreads();                    // all warps done reading Hs before reuse
    float* Cs = (float*)Hs;
    store_matrix_sync(&Cs[(wr * 16) * CS_STRIDE + wc * 32],      fc0, CS_STRIDE, mem_row_major);
    store_matrix_sync(&Cs[(wr * 16) * CS_STRIDE + wc * 32 + 16], fc1, CS_STRIDE, mem_row_major);
    __syncthreads();

    // guarded epilogue: + deg*b2, never writes past M
#pragma unroll
    for (int i = 0; i < 4; i++) {
        int s = tid + i * 256;          // 0..1023 float4 slots
        int r = s >> 4;
        int c4 = (s & 15) * 4;
        int gr = rowBase + r;
        if (gr < M) {
            float rs = (float)deg[gr];
            float4 v = *(float4*)&Cs[r * CS_STRIDE + c4];
            int c = colBase + c4;
            v.x = fmaf(rs, b2[c + 0], v.x);
            v.y = fmaf(rs, b2[c + 1], v.y);
            v.z = fmaf(rs, b2[c + 2], v.z);
            v.w = fmaf(rs, b2[c + 3], v.w);
            *(float4*)(Cg + (size_t)gr * CH + c) = v;
        }
    }
}

// ---------------- edge aggregation: R9-proven (fp32 A, f32x2), fp16 H out -------
__global__ __launch_bounds__(256)
void edge_kernel(const float* __restrict__ A, const float* __restrict__ Bpb,
                 const int* __restrict__ cnt, const ull* __restrict__ pay,
                 __half2* __restrict__ Hh, int N) {
    int w = (blockIdx.x * blockDim.x + threadIdx.x) >> 5;
    int lane = threadIdx.x & 31;
    if (w >= N) return;
    int c4 = lane * 4;

    ulonglong2 bvp = *(const ulonglong2*)(Bpb + (size_t)w * CH + c4);
    ull bv0 = bvp.x, bv1 = bvp.y;
    ull acc0 = 0ull, acc1 = 0ull;

    int n = cnt[w];
    if (n > SLOTS) n = SLOTS;
    size_t base = (size_t)w << 8;

    for (int j = 0; j < n; j += 32) {
        ull p = 0;
        if (j + lane < n) p = pay[base + j + lane];
        int m = n - j; if (m > 32) m = 32;
        for (int k = 0; k < m; k++) {
            ull pk = __shfl_sync(0xFFFFFFFFu, p, k);
            unsigned rbits = (unsigned)pk;
            unsigned abits = (unsigned)(pk >> 32);
            ull aa;
            asm("mov.b64 %0, {%1, %1};" : "=l"(aa) : "r"(abits));
            ulonglong2 av = *(const ulonglong2*)(A + ((size_t)rbits << 7) + c4);
            ull t0, t1;
            asm("fma.rn.f32x2 %0, %1, %2, %3;" : "=l"(t0) : "l"(aa), "l"(av.x), "l"(bv0));
            asm("fma.rn.f32x2 %0, %1, %2, %3;" : "=l"(t1) : "l"(aa), "l"(av.y), "l"(bv1));
            unsigned lo0, hi0, lo1, hi1;
            asm("mov.b64 {%0, %1}, %2;" : "=r"(lo0), "=r"(hi0) : "l"(t0));
            asm("mov.b64 {%0, %1}, %2;" : "=r"(lo1), "=r"(hi1) : "l"(t1));
            lo0 = __float_as_uint(fmaxf(__uint_as_float(lo0), 0.f));
            hi0 = __float_as_uint(fmaxf(__uint_as_float(hi0), 0.f));
            lo1 = __float_as_uint(fmaxf(__uint_as_float(lo1), 0.f));
            hi1 = __float_as_uint(fmaxf(__uint_as_float(hi1), 0.f));
            asm("mov.b64 %0, {%1, %2};" : "=l"(t0) : "r"(lo0), "r"(hi0));
            asm("mov.b64 %0, {%1, %2};" : "=l"(t1) : "r"(lo1), "r"(hi1));
            asm("add.rn.f32x2 %0, %1, %2;" : "=l"(acc0) : "l"(acc0), "l"(t0));
            asm("add.rn.f32x2 %0, %1, %2;" : "=l"(acc1) : "l"(acc1), "l"(t1));
        }
    }
    float f0, f1, f2, f3;
    asm("mov.b64 {%0, %1}, %2;" : "=f"(f0), "=f"(f1) : "l"(acc0));
    asm("mov.b64 {%0, %1}, %2;" : "=f"(f2), "=f"(f3) : "l"(acc1));
    __half2 h0 = __floats2half2_rn(f0, f1);
    __half2 h1 = __floats2half2_rn(f2, f3);
    uint2 o; o.x = *(unsigned*)&h0; o.y = *(unsigned*)&h1;
    *(uint2*)((__half*)Hh + (size_t)w * CH + c4) = o;
}

// ---------------- launch ----------------
extern "C" void kernel_launch(void* const* d_in, const int* in_sizes, int n_in,
                              void* d_out, int out_size) {
    const float* x  = (const float*)d_in[0];
    const int*   ei = (const int*)d_in[1];     // int32 [2, E]
    const float* ea = (const float*)d_in[2];
    const float* W1 = (const float*)d_in[3];
    const float* b1 = (const float*)d_in[4];
    const float* W2 = (const float*)d_in[5];
    const float* b2 = (const float*)d_in[6];
    float* out = (float*)d_out;

    int N = in_sizes[0] / CH;
    int E = in_sizes[2];

    float *pA, *pBp;
    __half2 *pHh;
    int *pcnt;
    ull *ppay;
    cudaGetSymbolAddress((void**)&pA,   g_A);
    cudaGetSymbolAddress((void**)&pBp,  g_Bp);
    cudaGetSymbolAddress((void**)&pHh,  g_Hh);
    cudaGetSymbolAddress((void**)&pcnt, g_cnt);
    cudaGetSymbolAddress((void**)&ppay, g_pay);

    // bucket scatter (by receiving node = col)
    zero_cnt_kernel<<<(N + 255) / 256, 256>>>(pcnt, N);
    int sthreads = (E + 3) / 4;
    scatter_kernel<<<(sthreads + 255) / 256, 256>>>(ei, ea, pcnt, ppay, E);

    // node-level GEMMs on tensor cores
    dim3 g1((N + 63) / 64, 4);
    gemm_w1_wmma<<<g1, 256>>>(x, W1, b1, pA, pBp, N);

    // per-node ReLU-message aggregation (warp per node)
    edge_kernel<<<(N * 32 + 255) / 256, 256>>>(pA, pBp, pcnt, ppay, pHh, N);

    // out = H @ W2 + deg * b2
    dim3 g2((N + 63) / 64, CH / 64);
    gemm_out_wmma<<<g2, 256>>>(pHh, W2, out, N, pcnt, b2);
}

// round 13
// speedup vs baseline: 1.7235x; 1.0457x over previous
#include <cuda_runtime.h>
#include <cuda_fp16.h>
#include <mma.h>

using namespace nvcuda::wmma;

#define CH      128
#define NMAX    10000
#define EMAX    640000
#define SLOTS   256
#define PADROWS 64

#define XH_STRIDE 136
#define WH_STRIDE 72
#define CS_STRIDE 68

typedef unsigned long long ull;

// ---------------- device scratch ----------------
__device__ __align__(16) float   g_A [(NMAX + PADROWS) * CH];  // x @ W1[:128]
__device__ __align__(16) float   g_Bp[(NMAX + PADROWS) * CH];  // x @ W1[128:] + b1
__device__ __align__(16) __half2 g_Hh[NMAX * CH / 2];          // fp16 aggregated hidden
__device__ int g_cnt[NMAX];          // statically zero; edge_kernel re-zeros each run
__device__ int g_deg[NMAX];          // degree snapshot for gemm_out bias
__device__ __align__(16) ull g_pay[(size_t)NMAX * SLOTS];

// ---------------- fused prep: blocks [0,gemmBlocks) = dual W1 GEMM; rest = scatter ----
__global__ __launch_bounds__(256)
void prep_kernel(const float* __restrict__ X, const float* __restrict__ W1,
                 const float* __restrict__ b1,
                 float* __restrict__ Aout, float* __restrict__ Bpout, int M,
                 const int* __restrict__ ei, const float* __restrict__ ea,
                 int* __restrict__ cnt, ull* __restrict__ pay, int E,
                 int gemmBlocks, int nx) {
    __shared__ __align__(16) __half Xh[64 * XH_STRIDE];
    __shared__ __align__(16) __half Wh[128 * WH_STRIDE];
    __shared__ __align__(16) float  bias_t[16 * 64];

    int tid = threadIdx.x;

    if (blockIdx.x >= gemmBlocks) {
        // ---------------- scatter role ----------------
        int bid = blockIdx.x - gemmBlocks;
        int i0 = (bid * 256 + tid) * 4;
        if (i0 + 3 < E) {
            int4   rows = *(const int4*)(ei + i0);
            int4   cols = *(const int4*)(ei + E + i0);
            float4 a    = *(const float4*)(ea + i0);
            int   r[4] = {rows.x, rows.y, rows.z, rows.w};
            int   c[4] = {cols.x, cols.y, cols.z, cols.w};
            float v[4] = {a.x, a.y, a.z, a.w};
#pragma unroll
            for (int k = 0; k < 4; k++) {
                int slot = atomicAdd(cnt + c[k], 1);
                if (slot < SLOTS)
                    pay[((size_t)c[k] << 8) + slot] =
                        ((ull)__float_as_uint(v[k]) << 32) | (unsigned)r[k];
            }
        } else {
            for (int i = i0; i < E; i++) {
                int c = ei[E + i];
                int slot = atomicAdd(cnt + c, 1);
                if (slot < SLOTS)
                    pay[((size_t)c << 8) + slot] =
                        ((ull)__float_as_uint(ea[i]) << 32) | (unsigned)ei[i];
            }
        }
        return;
    }

    // ---------------- WMMA dual GEMM role ----------------
    int bx = blockIdx.x % nx;
    int ct = blockIdx.x / nx;           // 0..3
    int which = ct >> 1;                // 0 -> Aout, 1 -> Bpout
    int ncol = (ct & 1) * 64;
    const float* W = W1 + which * CH * CH;
    int rowBase = bx * 64;

    // X tile 64x128 -> fp16 smem
#pragma unroll
    for (int i = 0; i < 8; i++) {
        int s = tid + i * 256;
        int r = s >> 5;
        int c4 = (s & 31) * 4;
        float4 v = make_float4(0.f, 0.f, 0.f, 0.f);
        int gr = rowBase + r;
        if (gr < M) v = *(const float4*)(X + (size_t)gr * CH + c4);
        __half2 h0 = __floats2half2_rn(v.x, v.y);
        __half2 h1 = __floats2half2_rn(v.z, v.w);
        uint2 u; u.x = *(unsigned*)&h0; u.y = *(unsigned*)&h1;
        *(uint2*)&Xh[r * XH_STRIDE + c4] = u;
    }
    // W tile 128x64 -> fp16 smem
#pragma unroll
    for (int i = 0; i < 8; i++) {
        int s = tid + i * 256;
        int r = s >> 4;
        int c4 = (s & 15) * 4;
        float4 v = *(const float4*)(W + (size_t)r * CH + ncol + c4);
        __half2 h0 = __floats2half2_rn(v.x, v.y);
        __half2 h1 = __floats2half2_rn(v.z, v.w);
        uint2 u; u.x = *(unsigned*)&h0; u.y = *(unsigned*)&h1;
        *(uint2*)&Wh[r * WH_STRIDE + c4] = u;
    }
    if (which) {
#pragma unroll
        for (int i = 0; i < 4; i++) {
            int s = tid + i * 256;
            bias_t[s] = b1[ncol + (s & 63)];
        }
    }
    __syncthreads();

    int wid = tid >> 5;
    int wr = wid >> 1;
    int wc = wid & 1;

    fragment<accumulator, 16, 16, 16, float> fc0, fc1;
    if (which) {
        load_matrix_sync(fc0, &bias_t[wc * 32], 64, mem_row_major);
        load_matrix_sync(fc1, &bias_t[wc * 32 + 16], 64, mem_row_major);
    } else {
        fill_fragment(fc0, 0.f);
        fill_fragment(fc1, 0.f);
    }

#pragma unroll
    for (int k0 = 0; k0 < 128; k0 += 16) {
        fragment<matrix_a, 16, 16, 16, __half, row_major> fa;
        fragment<matrix_b, 16, 16, 16, __half, row_major> fb0, fb1;
        load_matrix_sync(fa, &Xh[wr * 16 * XH_STRIDE + k0], XH_STRIDE);
        load_matrix_sync(fb0, &Wh[k0 * WH_STRIDE + wc * 32], WH_STRIDE);
        load_matrix_sync(fb1, &Wh[k0 * WH_STRIDE + wc * 32 + 16], WH_STRIDE);
        mma_sync(fc0, fa, fb0, fc0);
        mma_sync(fc1, fa, fb1, fc1);
    }

    float* Cout = which ? Bpout : Aout;
    int gr0 = rowBase + wr * 16;        // padded buffers: OOB rows land in pad
    store_matrix_sync(Cout + (size_t)gr0 * CH + ncol + wc * 32,      fc0, CH, mem_row_major);
    store_matrix_sync(Cout + (size_t)gr0 * CH + ncol + wc * 32 + 16, fc1, CH, mem_row_major);
}

// ---------------- edge aggregation: warp/node, f32x2 math; consumes+resets cnt ----
__global__ __launch_bounds__(256)
void edge_kernel(const float* __restrict__ A, const float* __restrict__ Bpb,
                 int* __restrict__ cnt, int* __restrict__ deg,
                 const ull* __restrict__ pay, __half2* __restrict__ Hh, int N) {
    int w = (blockIdx.x * blockDim.x + threadIdx.x) >> 5;
    int lane = threadIdx.x & 31;
    if (w >= N) return;
    int c4 = lane * 4;

    ulonglong2 bvp = *(const ulonglong2*)(Bpb + (size_t)w * CH + c4);
    ull bv0 = bvp.x, bv1 = bvp.y;
    ull acc0 = 0ull, acc1 = 0ull;

    int n = cnt[w];
    if (lane == 0) { deg[w] = n; cnt[w] = 0; }   // snapshot degree, reset for next replay
    if (n > SLOTS) n = SLOTS;
    size_t base = (size_t)w << 8;

    for (int j = 0; j < n; j += 32) {
        ull p = 0;
        if (j + lane < n) p = pay[base + j + lane];
        int m = n - j; if (m > 32) m = 32;
        for (int k = 0; k < m; k++) {
            ull pk = __shfl_sync(0xFFFFFFFFu, p, k);
            unsigned rbits = (unsigned)pk;
            unsigned abits = (unsigned)(pk >> 32);
            ull aa;
            asm("mov.b64 %0, {%1, %1};" : "=l"(aa) : "r"(abits));
            ulonglong2 av = *(const ulonglong2*)(A + ((size_t)rbits << 7) + c4);
            ull t0, t1;
            asm("fma.rn.f32x2 %0, %1, %2, %3;" : "=l"(t0) : "l"(aa), "l"(av.x), "l"(bv0));
            asm("fma.rn.f32x2 %0, %1, %2, %3;" : "=l"(t1) : "l"(aa), "l"(av.y), "l"(bv1));
            unsigned lo0, hi0, lo1, hi1;
            asm("mov.b64 {%0, %1}, %2;" : "=r"(lo0), "=r"(hi0) : "l"(t0));
            asm("mov.b64 {%0, %1}, %2;" : "=r"(lo1), "=r"(hi1) : "l"(t1));
            lo0 = __float_as_uint(fmaxf(__uint_as_float(lo0), 0.f));
            hi0 = __float_as_uint(fmaxf(__uint_as_float(hi0), 0.f));
            lo1 = __float_as_uint(fmaxf(__uint_as_float(lo1), 0.f));
            hi1 = __float_as_uint(fmaxf(__uint_as_float(hi1), 0.f));
            asm("mov.b64 %0, {%1, %2};" : "=l"(t0) : "r"(lo0), "r"(hi0));
            asm("mov.b64 %0, {%1, %2};" : "=l"(t1) : "r"(lo1), "r"(hi1));
            asm("add.rn.f32x2 %0, %1, %2;" : "=l"(acc0) : "l"(acc0), "l"(t0));
            asm("add.rn.f32x2 %0, %1, %2;" : "=l"(acc1) : "l"(acc1), "l"(t1));
        }
    }
    float f0, f1, f2, f3;
    asm("mov.b64 {%0, %1}, %2;" : "=f"(f0), "=f"(f1) : "l"(acc0));
    asm("mov.b64 {%0, %1}, %2;" : "=f"(f2), "=f"(f3) : "l"(acc1));
    __half2 h0 = __floats2half2_rn(f0, f1);
    __half2 h1 = __floats2half2_rn(f2, f3);
    uint2 o; o.x = *(unsigned*)&h0; o.y = *(unsigned*)&h1;
    *(uint2*)((__half*)Hh + (size_t)w * CH + c4) = o;
}

// ---------------- GEMM 2 (WMMA): out = H @ W2 + deg[m]*b2[n] -------------------
__global__ __launch_bounds__(256)
void gemm_out_wmma(const __half2* __restrict__ Hh, const float* __restrict__ W2,
                   float* __restrict__ Cg, int M,
                   const int* __restrict__ deg, const float* __restrict__ b2) {
    __shared__ __align__(16) __half Hs[64 * XH_STRIDE];   // reused as float Cs[64][68]
    __shared__ __align__(16) __half Ws[128 * WH_STRIDE];

    int tid = threadIdx.x;
    int rowBase = blockIdx.x * 64;
    int colBase = blockIdx.y * 64;

#pragma unroll
    for (int i = 0; i < 8; i++) {
        int s = tid + i * 256;
        int r = s >> 5;
        int ch4 = (s & 31) * 4;
        uint2 u = make_uint2(0u, 0u);
        int gr = rowBase + r;
        if (gr < M) u = *(const uint2*)((const __half*)Hh + (size_t)gr * CH + ch4);
        *(uint2*)&Hs[r * XH_STRIDE + ch4] = u;
    }
#pragma unroll
    for (int i = 0; i < 8; i++) {
        int s = tid + i * 256;
        int r = s >> 4;
        int c4 = (s & 15) * 4;
        float4 v = *(const float4*)(W2 + (size_t)r * CH + colBase + c4);
        __half2 h0 = __floats2half2_rn(v.x, v.y);
        __half2 h1 = __floats2half2_rn(v.z, v.w);
        uint2 u; u.x = *(unsigned*)&h0; u.y = *(unsigned*)&h1;
        *(uint2*)&Ws[r * WH_STRIDE + c4] = u;
    }
    __syncthreads();

    int wid = tid >> 5;
    int wr = wid >> 1;
    int wc = wid & 1;

    fragment<accumulator, 16, 16, 16, float> fc0, fc1;
    fill_fragment(fc0, 0.f);
    fill_fragment(fc1, 0.f);

#pragma unroll
    for (int k0 = 0; k0 < 128; k0 += 16) {
        fragment<matrix_a, 16, 16, 16, __half, row_major> fa;
        fragment<matrix_b, 16, 16, 16, __half, row_major> fb0, fb1;
        load_matrix_sync(fa, &Hs[wr * 16 * XH_STRIDE + k0], XH_STRIDE);
        load_matrix_sync(fb0, &Ws[k0 * WH_STRIDE + wc * 32], WH_STRIDE);
        load_matrix_sync(fb1, &Ws[k0 * WH_STRIDE + wc * 32 + 16], WH_STRIDE);
        mma_sync(fc0, fa, fb0, fc0);
        mma_sync(fc1, fa, fb1, fc1);
    }

    __syncthreads();
    float* Cs = (float*)Hs;
    store_matrix_sync(&Cs[(wr * 16) * CS_STRIDE + wc * 32],      fc0, CS_STRIDE, mem_row_major);
    store_matrix_sync(&Cs[(wr * 16) * CS_STRIDE + wc * 32 + 16], fc1, CS_STRIDE, mem_row_major);
    __syncthreads();

#pragma unroll
    for (int i = 0; i < 4; i++) {
        int s = tid + i * 256;
        int r = s >> 4;
        int c4 = (s & 15) * 4;
        int gr = rowBase + r;
        if (gr < M) {
            float rs = (float)deg[gr];
            float4 v = *(float4*)&Cs[r * CS_STRIDE + c4];
            int c = colBase + c4;
            v.x = fmaf(rs, b2[c + 0], v.x);
            v.y = fmaf(rs, b2[c + 1], v.y);
            v.z = fmaf(rs, b2[c + 2], v.z);
            v.w = fmaf(rs, b2[c + 3], v.w);
            *(float4*)(Cg + (size_t)gr * CH + c) = v;
        }
    }
}

// ---------------- launch ----------------
extern "C" void kernel_launch(void* const* d_in, const int* in_sizes, int n_in,
                              void* d_out, int out_size) {
    const float* x  = (const float*)d_in[0];
    const int*   ei = (const int*)d_in[1];     // int32 [2, E]
    const float* ea = (const float*)d_in[2];
    const float* W1 = (const float*)d_in[3];
    const float* b1 = (const float*)d_in[4];
    const float* W2 = (const float*)d_in[5];
    const float* b2 = (const float*)d_in[6];
    float* out = (float*)d_out;

    int N = in_sizes[0] / CH;
    int E = in_sizes[2];

    float *pA, *pBp;
    __half2 *pHh;
    int *pcnt, *pdeg;
    ull *ppay;
    cudaGetSymbolAddress((void**)&pA,   g_A);
    cudaGetSymbolAddress((void**)&pBp,  g_Bp);
    cudaGetSymbolAddress((void**)&pHh,  g_Hh);
    cudaGetSymbolAddress((void**)&pcnt, g_cnt);
    cudaGetSymbolAddress((void**)&pdeg, g_deg);
    cudaGetSymbolAddress((void**)&ppay, g_pay);

    // fused: dual W1 GEMM (tensor) + bucket scatter (atomics), independent roles
    int nx = (N + 63) / 64;
    int gemmBlocks = nx * 4;
    int scatBlocks = ((E + 3) / 4 + 255) / 256;
    prep_kernel<<<gemmBlocks + scatBlocks, 256>>>(
        x, W1, b1, pA, pBp, N, ei, ea, pcnt, ppay, E, gemmBlocks, nx);

    // per-node ReLU-message aggregation (warp per node); snapshots deg, resets cnt
    edge_kernel<<<(N * 32 + 255) / 256, 256>>>(pA, pBp, pcnt, pdeg, ppay, pHh, N);

    // out = H @ W2 + deg * b2
    dim3 g2((N + 63) / 64, CH / 64);
    gemm_out_wmma<<<g2, 256>>>(pHh, W2, out, N, pdeg, b2);
}